// round 13
// baseline (speedup 1.0000x reference)
#include <cuda_runtime.h>
#include <math.h>

typedef unsigned long long U64;

// ---------------- device scratch (static, no runtime allocs) ----------------
__device__ float g_cv[4 * 288 * 512];            // (B,T,V) rolling CV
__device__ float g_imp[4 * 288];                 // (B,T) summed event impact
__device__ float g_cb[4 * 32 * 288 * 512];       // (B,C,T,V) pooled combination
struct WPack {
    ulonglong2 wd[1024];   // [c][o] = {dup(w1+I), dup(w2)}
    U64 bd[32];            // dup bias
};
__device__ WPack g_wp;
__constant__ WPack c_wp;

// ---------------- packed f32x2 helpers (sm_103a) ----------------
static __device__ __forceinline__ U64 pack2(float x) {
    unsigned int u = __float_as_uint(x);
    U64 r;
    asm("mov.b64 %0, {%1, %2};" : "=l"(r) : "r"(u), "r"(u));
    return r;
}
static __device__ __forceinline__ U64 fma2(U64 a, U64 b, U64 c) {
    U64 d;
    asm("fma.rn.f32x2 %0, %1, %2, %3;" : "=l"(d) : "l"(a), "l"(b), "l"(c));
    return d;
}
static __device__ __forceinline__ U64 add2(U64 a, U64 b) {
    U64 d;
    asm("add.rn.f32x2 %0, %1, %2;" : "=l"(d) : "l"(a), "l"(b));
    return d;
}
static __device__ __forceinline__ U64 mul2(U64 a, U64 b) {
    U64 d;
    asm("mul.rn.f32x2 %0, %1, %2;" : "=l"(d) : "l"(a), "l"(b));
    return d;
}

// ================= kernel A: prep blocks FIRST, then scan/pool blocks =================
// blocks [0, 48):    rolling CV       (wave 1 -> overlapped by the scan body)
// blocks [48, 52):   event impact     (events staged through SMEM)
// block  52:         weight packing
// blocks [53, 2101): per-(b,c,vtile) full-T prefix scan + pooled combination
__global__ void __launch_bounds__(256)
scan_kernel(const float* __restrict__ x,
            const float* __restrict__ flow,
            const float* __restrict__ events,
            const float* __restrict__ ef,
            const float* __restrict__ w1,
            const float* __restrict__ b1,
            const float* __restrict__ w2,
            const float* __restrict__ b2,
            const float* __restrict__ fusion_w,
            const float* __restrict__ fusion_b) {
    __shared__ U64 s_ps[289][16];   // 37KB (also reused by the impact branch)
    __shared__ float s_h[32];
    __shared__ float s_lg[5];

    const int bid = blockIdx.x;
    const int tid = threadIdx.x;

    if (bid < 53) {
        if (bid < 48) {
            // ---- rolling CV: (b, 24-t chunk), thread covers v=tid and v=tid+256
            const int b = bid / 12;
            const int c0 = (bid % 12) * 24;
            const float* f0 = flow + (size_t)b * 288 * 512 + tid;
            const float* f1 = f0 + 256;
            int tstart = c0 - 59; if (tstart < 0) tstart = 0;
            float sA = 0.f, s2A = 0.f, sB = 0.f, s2B = 0.f;
            for (int t = tstart; t < c0 + 24; t++) {
                float a0 = f0[(size_t)t * 512];
                float a1 = f1[(size_t)t * 512];
                int to = t - 60;
                float o0 = 0.f, o1 = 0.f;
                bool sub = (to >= tstart);
                if (sub) { o0 = f0[(size_t)to * 512]; o1 = f1[(size_t)to * 512]; }
                sA += a0; s2A += a0 * a0; sB += a1; s2B += a1 * a1;
                if (sub) { sA -= o0; s2A -= o0 * o0; sB -= o1; s2B -= o1 * o1; }
                if (t >= c0) {
                    float cv0 = 0.f, cv1 = 0.f;
                    if (t >= 59) {
                        float m0 = sA * (1.f / 60.f);
                        float v0 = (s2A - 60.f * m0 * m0) * (1.f / 59.f);
                        cv0 = sqrtf(fmaxf(v0, 0.f)) / (m0 + 1e-6f);
                        float m1 = sB * (1.f / 60.f);
                        float v1 = (s2B - 60.f * m1 * m1) * (1.f / 59.f);
                        cv1 = sqrtf(fmaxf(v1, 0.f)) / (m1 + 1e-6f);
                    }
                    size_t o = ((size_t)b * 288 + t) * 512 + tid;
                    g_cv[o] = cv0;
                    g_cv[o + 256] = cv1;
                }
            }
        } else if (bid < 52) {
            // ---- event impact: stage events[b] into SMEM, suffix-sum from SMEM
            const int b = bid - 48;
            float* s_ev = (float*)s_ps;   // 864 floats
            for (int i = tid; i < 864; i += 256)
                s_ev[i] = events[(size_t)b * 864 + i];
            __syncthreads();
            const float r0 = expf(-1.f / 300.f), r1 = expf(-1.f / 600.f),
                        r2 = expf(-1.f / 180.f);
            #pragma unroll
            for (int half = 0; half < 2; half++) {
                int t = tid + half * 256;
                if (t < 288) {
                    float w0 = 0.3f, w1v = 0.5f, w2v = 0.2f;
                    float a0 = 0.f, a1 = 0.f, a2 = 0.f;
                    for (int s = t; s < 288; s++) {
                        const float* e = s_ev + s * 3;
                        a0 = fmaf(e[0], w0, a0);
                        a1 = fmaf(e[1], w1v, a1);
                        a2 = fmaf(e[2], w2v, a2);
                        w0 *= r0; w1v *= r1; w2v *= r2;
                    }
                    g_imp[b * 288 + t] = a0 + a1 + a2;
                }
            }
        } else {
            // ---- weight packing (residual identity folded into w1)
            for (int i = tid; i < 1024; i += 256) {
                int c = i >> 5, o = i & 31;
                float a = fusion_w[o * 64 + c] + ((o == c) ? 1.f : 0.f);
                float bw = fusion_w[o * 64 + 32 + c];
                ulonglong2 p;
                p.x = pack2(a);
                p.y = pack2(bw);
                g_wp.wd[i] = p;
            }
            if (tid < 32) g_wp.bd[tid] = pack2(fusion_b[tid]);
        }
        return;
    }

    // ---------------- scan/pool block ----------------
    const int sid = bid - 53;
    const int v0 = (sid & 15) * 32;        // 16 v-pairs
    const int c  = (sid >> 4) & 31;
    const int b  = sid >> 9;

    // load full T column for this (b,c,v-tile)
    const float* xb = x + ((size_t)(b * 32 + c) * 288) * 512 + v0;
    #pragma unroll
    for (int k = 0; k < 18; k++) {
        int idx = tid + k * 256;
        int r = idx >> 4, cl = idx & 15;
        s_ps[1 + r][cl] = *(const U64*)(xb + (size_t)r * 512 + cl * 2);
    }
    if (tid < 16) s_ps[0][tid] = 0ull;

    // gate MLP hidden layer (inline; no prep dependency)
    if (tid < 32) {
        float a = b1[tid];
        #pragma unroll
        for (int i = 0; i < 8; i++) a += ef[b * 8 + i] * w1[i * 32 + tid];
        s_h[tid] = fmaxf(a, 0.f);
    }
    __syncthreads();

    if (tid < 5) {
        float a = b2[tid];
        #pragma unroll
        for (int i = 0; i < 32; i++) a += s_h[i] * w2[i * 5 + tid];
        s_lg[tid] = 1.f / (1.f + expf(-a));
    }

    // phase 1: in-segment inclusive scan (16 segments x 18 rows)
    const int seg = tid >> 4, cl = tid & 15;
    {
        int r0 = 1 + seg * 18;
        U64 run = 0ull;
        #pragma unroll
        for (int i = 0; i < 18; i++) {
            run = add2(run, s_ps[r0 + i][cl]);
            s_ps[r0 + i][cl] = run;
        }
    }
    __syncthreads();

    // phase 2a: per-thread segment-offset gather
    U64 off = 0ull;
    if (seg > 0) {
        off = s_ps[18][cl];
        for (int s = 2; s <= seg; s++) off = add2(off, s_ps[18 * s][cl]);
    }
    __syncthreads();

    // phase 2b: apply offsets; finalize gate weights in registers
    if (seg > 0) {
        int r0 = 1 + seg * 18;
        #pragma unroll
        for (int i = 0; i < 18; i++)
            s_ps[r0 + i][cl] = add2(s_ps[r0 + i][cl], off);
    }
    float lg0 = s_lg[0], lg1 = s_lg[1], lg2 = s_lg[2], lg3 = s_lg[3], lg4 = s_lg[4];
    float mx = fmaxf(fmaxf(fmaxf(lg0, lg1), fmaxf(lg2, lg3)), lg4);
    float e0 = expf(lg0 - mx), e1 = expf(lg1 - mx), e2 = expf(lg2 - mx),
          e3 = expf(lg3 - mx), e4 = expf(lg4 - mx);
    float inv = 1.f / (e0 + e1 + e2 + e3 + e4);
    U64 cw[5];
    cw[0] = pack2(e0 * inv * (1.f / 3.f));
    cw[1] = pack2(e1 * inv * (1.f / 6.f));
    cw[2] = pack2(e2 * inv * (1.f / 12.f));
    cw[3] = pack2(e3 * inv * (1.f / 24.f));
    cw[4] = pack2(e4 * inv * (1.f / 48.f));
    __syncthreads();

    // compute cb for all (t, v-pair) and store
    const U64 neg1 = pack2(-1.f);
    float* cbase = g_cb + ((size_t)(b * 32 + c) * 288) * 512 + v0;
    #pragma unroll
    for (int k = 0; k < 18; k++) {
        int idx = tid + k * 256;
        int t = idx >> 4, cl2 = idx & 15;
        int a3  = max(t - 1, 0),  b3  = min(t + 2, 288);
        int a6  = max(t - 3, 0),  b6  = min(t + 3, 288);
        int a12 = max(t - 6, 0),  b12 = min(t + 6, 288);
        int a24 = max(t - 12, 0), b24 = min(t + 12, 288);
        int a48 = max(t - 24, 0), b48 = min(t + 24, 288);
        U64 d0 = fma2(neg1, s_ps[a3][cl2],  s_ps[b3][cl2]);
        U64 d1 = fma2(neg1, s_ps[a6][cl2],  s_ps[b6][cl2]);
        U64 d2 = fma2(neg1, s_ps[a12][cl2], s_ps[b12][cl2]);
        U64 d3 = fma2(neg1, s_ps[a24][cl2], s_ps[b24][cl2]);
        U64 d4 = fma2(neg1, s_ps[a48][cl2], s_ps[b48][cl2]);
        U64 cb = mul2(cw[0], d0);
        cb = fma2(cw[1], d1, cb);
        cb = fma2(cw[2], d2, cb);
        cb = fma2(cw[3], d3, cb);
        cb = fma2(cw[4], d4, cb);
        *(U64*)(cbase + (size_t)t * 512 + cl2 * 2) = cb;
    }
}

// ---------------- kernel B: pointwise 64->32 projection ----------------
// Thread = (8 outputs) x (2 t-points) x (2 v-pairs, float4 loads).
// Per channel: 4 LDG.128 + 8 LDC.128 -> 64 FMA2. LSU instr count halved vs
// the LDG.64 version; one LDC.128 still feeds 8 FMA2. No L2 prefetch (it
// doubled LSU dispatch traffic for no latency win).
__global__ void __launch_bounds__(256, 2)
proj_kernel(const float* __restrict__ x, float* __restrict__ out) {
    const int tid  = threadIdx.x;
    const int vq   = tid & 63;           // v-quad (4 floats = 2 pairs)
    const int og   = tid >> 6;           // output group 0..3 (8 outputs each)
    const int t0   = blockIdx.y * 2;
    const int b    = blockIdx.z;
    const size_t CH = (size_t)288 * 512;

    const size_t base = ((size_t)b * 32 * 288 + t0) * 512
                        + blockIdx.x * 256 + vq * 4;
    const float* px  = x + base;
    const float* pcb = g_cb + base;

    // epilogue operands loaded up front (latency hidden under the c-loop)
    const float* pcv = g_cv + ((size_t)b * 288 + t0) * 512
                       + blockIdx.x * 256 + vq * 4;
    U64 m2[2][2], imp[2];
    #pragma unroll
    for (int p = 0; p < 2; p++) {
        ulonglong2 cvq = *(const ulonglong2*)(pcv + (size_t)p * 512);
        m2[p][0] = add2(pack2(1.f), cvq.x);
        m2[p][1] = add2(pack2(1.f), cvq.y);
        imp[p] = pack2(g_imp[b * 288 + t0 + p]);
    }

    // accumulators: [point][output][half]
    U64 acc[2][8][2];
    #pragma unroll
    for (int p = 0; p < 2; p++)
        #pragma unroll
        for (int o = 0; o < 8; o++) {
            U64 bo = c_wp.bd[og * 8 + o];
            acc[p][o][0] = bo;
            acc[p][o][1] = bo;
        }

    // depth-1 register pipeline over channels (4 LDG.128 per channel)
    ulonglong2 xv[2], cb[2], xn[2], cn[2];
    #pragma unroll
    for (int p = 0; p < 2; p++) {
        xv[p] = *(const ulonglong2*)(px  + (size_t)p * 512);
        cb[p] = *(const ulonglong2*)(pcb + (size_t)p * 512);
    }
    for (int c = 0; c < 32; c++) {
        if (c < 31) {
            const float* nx  = px  + (size_t)(c + 1) * CH;
            const float* ncb = pcb + (size_t)(c + 1) * CH;
            #pragma unroll
            for (int p = 0; p < 2; p++) {
                xn[p] = *(const ulonglong2*)(nx  + (size_t)p * 512);
                cn[p] = *(const ulonglong2*)(ncb + (size_t)p * 512);
            }
        }
        const ulonglong2* wrow = c_wp.wd + c * 32 + og * 8;
        #pragma unroll
        for (int o = 0; o < 8; o++) {
            ulonglong2 w = wrow[o];          // one LDC.128 -> 8 FMA2
            #pragma unroll
            for (int p = 0; p < 2; p++) {
                acc[p][o][0] = fma2(w.x, xv[p].x, acc[p][o][0]);
                acc[p][o][1] = fma2(w.x, xv[p].y, acc[p][o][1]);
                acc[p][o][0] = fma2(w.y, cb[p].x, acc[p][o][0]);
                acc[p][o][1] = fma2(w.y, cb[p].y, acc[p][o][1]);
            }
        }
        #pragma unroll
        for (int p = 0; p < 2; p++) { xv[p] = xn[p]; cb[p] = cn[p]; }
    }

    // epilogue: out = acc * (1+cv) + impact   (STG.128)
    float* po = out + base + (size_t)(og * 8) * CH;
    #pragma unroll
    for (int o = 0; o < 8; o++)
        #pragma unroll
        for (int p = 0; p < 2; p++) {
            ulonglong2 r;
            r.x = fma2(acc[p][o][0], m2[p][0], imp[p]);
            r.y = fma2(acc[p][o][1], m2[p][1], imp[p]);
            *(ulonglong2*)(po + (size_t)o * CH + (size_t)p * 512) = r;
        }
}

// ---------------- launch ----------------
extern "C" void kernel_launch(void* const* d_in, const int* in_sizes, int n_in,
                              void* d_out, int out_size) {
    const float* flow   = (const float*)d_in[0];
    const float* events = (const float*)d_in[1];
    const float* x      = (const float*)d_in[2];
    const float* ef     = (const float*)d_in[3];
    const float* w1     = (const float*)d_in[4];
    const float* b1     = (const float*)d_in[5];
    const float* w2     = (const float*)d_in[6];
    const float* b2     = (const float*)d_in[7];
    const float* fw     = (const float*)d_in[8];
    const float* fb     = (const float*)d_in[9];
    float* out = (float*)d_out;

    scan_kernel<<<2101, 256>>>(x, flow, events, ef, w1, b1, w2, b2, fw, fb);

    void* src = nullptr;
    cudaGetSymbolAddress(&src, g_wp);
    cudaMemcpyToSymbolAsync(c_wp, src, sizeof(WPack), 0, cudaMemcpyDeviceToDevice);

    dim3 gB(2, 144, 4);   // (V/256, T/2, B)
    proj_kernel<<<gB, 256>>>(x, out);
}

// round 14
// speedup vs baseline: 1.0769x; 1.0769x over previous
#include <cuda_runtime.h>
#include <math.h>

typedef unsigned long long U64;

// ---------------- device scratch (static, no runtime allocs) ----------------
__device__ float g_cv[4 * 288 * 512];              // (B,T,V) rolling CV
__device__ float g_imp[4 * 288];                   // (B,T) summed event impact
__device__ unsigned short g_cbh[4 * 32 * 288 * 512]; // (B,C,T,V) pooled combo, bf16
struct WPack {
    ulonglong2 wd[1024];   // [c][o] = {dup(w1+I), dup(w2)}
    U64 bd[32];            // dup bias
};
__device__ WPack g_wp;
__constant__ WPack c_wp;

// ---------------- packed f32x2 helpers (sm_103a) ----------------
static __device__ __forceinline__ U64 pack2(float x) {
    unsigned int u = __float_as_uint(x);
    U64 r;
    asm("mov.b64 %0, {%1, %2};" : "=l"(r) : "r"(u), "r"(u));
    return r;
}
static __device__ __forceinline__ U64 fma2(U64 a, U64 b, U64 c) {
    U64 d;
    asm("fma.rn.f32x2 %0, %1, %2, %3;" : "=l"(d) : "l"(a), "l"(b), "l"(c));
    return d;
}
static __device__ __forceinline__ U64 add2(U64 a, U64 b) {
    U64 d;
    asm("add.rn.f32x2 %0, %1, %2;" : "=l"(d) : "l"(a), "l"(b));
    return d;
}
static __device__ __forceinline__ U64 mul2(U64 a, U64 b) {
    U64 d;
    asm("mul.rn.f32x2 %0, %1, %2;" : "=l"(d) : "l"(a), "l"(b));
    return d;
}
// f32x2 (U64) -> bf16x2 (u32), round-to-nearest
static __device__ __forceinline__ unsigned int cvt_bf16x2(U64 v) {
    unsigned int lo, hi, u;
    asm("mov.b64 {%0,%1}, %2;" : "=r"(lo), "=r"(hi) : "l"(v));
    asm("cvt.rn.satfinite.bf16x2.f32 %0, %1, %2;"
        : "=r"(u) : "f"(__uint_as_float(hi)), "f"(__uint_as_float(lo)));
    return u;
}
// bf16x2 (u32) -> f32x2 (U64) by mantissa shift (exact)
static __device__ __forceinline__ U64 bfexp(unsigned int u) {
    unsigned int lo = u << 16;
    unsigned int hi = u & 0xFFFF0000u;
    U64 r;
    asm("mov.b64 %0, {%1, %2};" : "=l"(r) : "r"(lo), "r"(hi));
    return r;
}

// ================= kernel A: prep blocks FIRST, then scan/pool blocks =================
// blocks [0, 48):    rolling CV       (wave 1 -> overlapped by the scan body)
// blocks [48, 52):   event impact     (events staged through SMEM)
// block  52:         weight packing
// blocks [53, 2101): per-(b,c,vtile) full-T prefix scan + pooled combination
__global__ void __launch_bounds__(256)
scan_kernel(const float* __restrict__ x,
            const float* __restrict__ flow,
            const float* __restrict__ events,
            const float* __restrict__ ef,
            const float* __restrict__ w1,
            const float* __restrict__ b1,
            const float* __restrict__ w2,
            const float* __restrict__ b2,
            const float* __restrict__ fusion_w,
            const float* __restrict__ fusion_b) {
    __shared__ U64 s_ps[289][16];   // 37KB (also reused by the impact branch)
    __shared__ float s_h[32];
    __shared__ float s_lg[5];

    const int bid = blockIdx.x;
    const int tid = threadIdx.x;

    if (bid < 53) {
        if (bid < 48) {
            // ---- rolling CV: (b, 24-t chunk), thread covers v=tid and v=tid+256
            const int b = bid / 12;
            const int c0 = (bid % 12) * 24;
            const float* f0 = flow + (size_t)b * 288 * 512 + tid;
            const float* f1 = f0 + 256;
            int tstart = c0 - 59; if (tstart < 0) tstart = 0;
            float sA = 0.f, s2A = 0.f, sB = 0.f, s2B = 0.f;
            for (int t = tstart; t < c0 + 24; t++) {
                float a0 = f0[(size_t)t * 512];
                float a1 = f1[(size_t)t * 512];
                int to = t - 60;
                float o0 = 0.f, o1 = 0.f;
                bool sub = (to >= tstart);
                if (sub) { o0 = f0[(size_t)to * 512]; o1 = f1[(size_t)to * 512]; }
                sA += a0; s2A += a0 * a0; sB += a1; s2B += a1 * a1;
                if (sub) { sA -= o0; s2A -= o0 * o0; sB -= o1; s2B -= o1 * o1; }
                if (t >= c0) {
                    float cv0 = 0.f, cv1 = 0.f;
                    if (t >= 59) {
                        float m0 = sA * (1.f / 60.f);
                        float v0 = (s2A - 60.f * m0 * m0) * (1.f / 59.f);
                        cv0 = sqrtf(fmaxf(v0, 0.f)) / (m0 + 1e-6f);
                        float m1 = sB * (1.f / 60.f);
                        float v1 = (s2B - 60.f * m1 * m1) * (1.f / 59.f);
                        cv1 = sqrtf(fmaxf(v1, 0.f)) / (m1 + 1e-6f);
                    }
                    size_t o = ((size_t)b * 288 + t) * 512 + tid;
                    g_cv[o] = cv0;
                    g_cv[o + 256] = cv1;
                }
            }
        } else if (bid < 52) {
            // ---- event impact: stage events[b] into SMEM, suffix-sum from SMEM
            const int b = bid - 48;
            float* s_ev = (float*)s_ps;   // 864 floats
            for (int i = tid; i < 864; i += 256)
                s_ev[i] = events[(size_t)b * 864 + i];
            __syncthreads();
            const float r0 = expf(-1.f / 300.f), r1 = expf(-1.f / 600.f),
                        r2 = expf(-1.f / 180.f);
            #pragma unroll
            for (int half = 0; half < 2; half++) {
                int t = tid + half * 256;
                if (t < 288) {
                    float w0 = 0.3f, w1v = 0.5f, w2v = 0.2f;
                    float a0 = 0.f, a1 = 0.f, a2 = 0.f;
                    for (int s = t; s < 288; s++) {
                        const float* e = s_ev + s * 3;
                        a0 = fmaf(e[0], w0, a0);
                        a1 = fmaf(e[1], w1v, a1);
                        a2 = fmaf(e[2], w2v, a2);
                        w0 *= r0; w1v *= r1; w2v *= r2;
                    }
                    g_imp[b * 288 + t] = a0 + a1 + a2;
                }
            }
        } else {
            // ---- weight packing (residual identity folded into w1)
            for (int i = tid; i < 1024; i += 256) {
                int c = i >> 5, o = i & 31;
                float a = fusion_w[o * 64 + c] + ((o == c) ? 1.f : 0.f);
                float bw = fusion_w[o * 64 + 32 + c];
                ulonglong2 p;
                p.x = pack2(a);
                p.y = pack2(bw);
                g_wp.wd[i] = p;
            }
            if (tid < 32) g_wp.bd[tid] = pack2(fusion_b[tid]);
        }
        return;
    }

    // ---------------- scan/pool block ----------------
    const int sid = bid - 53;
    const int v0 = (sid & 15) * 32;        // 16 v-pairs
    const int c  = (sid >> 4) & 31;
    const int b  = sid >> 9;

    // load full T column for this (b,c,v-tile)
    const float* xb = x + ((size_t)(b * 32 + c) * 288) * 512 + v0;
    #pragma unroll
    for (int k = 0; k < 18; k++) {
        int idx = tid + k * 256;
        int r = idx >> 4, cl = idx & 15;
        s_ps[1 + r][cl] = *(const U64*)(xb + (size_t)r * 512 + cl * 2);
    }
    if (tid < 16) s_ps[0][tid] = 0ull;

    // gate MLP hidden layer (inline; no prep dependency)
    if (tid < 32) {
        float a = b1[tid];
        #pragma unroll
        for (int i = 0; i < 8; i++) a += ef[b * 8 + i] * w1[i * 32 + tid];
        s_h[tid] = fmaxf(a, 0.f);
    }
    __syncthreads();

    if (tid < 5) {
        float a = b2[tid];
        #pragma unroll
        for (int i = 0; i < 32; i++) a += s_h[i] * w2[i * 5 + tid];
        s_lg[tid] = 1.f / (1.f + expf(-a));
    }

    // phase 1: in-segment inclusive scan (16 segments x 18 rows)
    const int seg = tid >> 4, cl = tid & 15;
    {
        int r0 = 1 + seg * 18;
        U64 run = 0ull;
        #pragma unroll
        for (int i = 0; i < 18; i++) {
            run = add2(run, s_ps[r0 + i][cl]);
            s_ps[r0 + i][cl] = run;
        }
    }
    __syncthreads();

    // phase 2a: per-thread segment-offset gather
    U64 off = 0ull;
    if (seg > 0) {
        off = s_ps[18][cl];
        for (int s = 2; s <= seg; s++) off = add2(off, s_ps[18 * s][cl]);
    }
    __syncthreads();

    // phase 2b: apply offsets; finalize gate weights in registers
    if (seg > 0) {
        int r0 = 1 + seg * 18;
        #pragma unroll
        for (int i = 0; i < 18; i++)
            s_ps[r0 + i][cl] = add2(s_ps[r0 + i][cl], off);
    }
    float lg0 = s_lg[0], lg1 = s_lg[1], lg2 = s_lg[2], lg3 = s_lg[3], lg4 = s_lg[4];
    float mx = fmaxf(fmaxf(fmaxf(lg0, lg1), fmaxf(lg2, lg3)), lg4);
    float e0 = expf(lg0 - mx), e1 = expf(lg1 - mx), e2 = expf(lg2 - mx),
          e3 = expf(lg3 - mx), e4 = expf(lg4 - mx);
    float inv = 1.f / (e0 + e1 + e2 + e3 + e4);
    U64 cw[5];
    cw[0] = pack2(e0 * inv * (1.f / 3.f));
    cw[1] = pack2(e1 * inv * (1.f / 6.f));
    cw[2] = pack2(e2 * inv * (1.f / 12.f));
    cw[3] = pack2(e3 * inv * (1.f / 24.f));
    cw[4] = pack2(e4 * inv * (1.f / 48.f));
    __syncthreads();

    // compute cb for all (t, v-pair) and store as bf16x2
    const U64 neg1 = pack2(-1.f);
    unsigned short* cbase = g_cbh + ((size_t)(b * 32 + c) * 288) * 512 + v0;
    #pragma unroll
    for (int k = 0; k < 18; k++) {
        int idx = tid + k * 256;
        int t = idx >> 4, cl2 = idx & 15;
        int a3  = max(t - 1, 0),  b3  = min(t + 2, 288);
        int a6  = max(t - 3, 0),  b6  = min(t + 3, 288);
        int a12 = max(t - 6, 0),  b12 = min(t + 6, 288);
        int a24 = max(t - 12, 0), b24 = min(t + 12, 288);
        int a48 = max(t - 24, 0), b48 = min(t + 24, 288);
        U64 d0 = fma2(neg1, s_ps[a3][cl2],  s_ps[b3][cl2]);
        U64 d1 = fma2(neg1, s_ps[a6][cl2],  s_ps[b6][cl2]);
        U64 d2 = fma2(neg1, s_ps[a12][cl2], s_ps[b12][cl2]);
        U64 d3 = fma2(neg1, s_ps[a24][cl2], s_ps[b24][cl2]);
        U64 d4 = fma2(neg1, s_ps[a48][cl2], s_ps[b48][cl2]);
        U64 cb = mul2(cw[0], d0);
        cb = fma2(cw[1], d1, cb);
        cb = fma2(cw[2], d2, cb);
        cb = fma2(cw[3], d3, cb);
        cb = fma2(cw[4], d4, cb);
        *(unsigned int*)(cbase + (size_t)t * 512 + cl2 * 2) = cvt_bf16x2(cb);
    }
}

// ---------------- kernel B: pointwise 64->32 projection ----------------
// Thread = (8 outputs) x (2 t-points) x (2 v-pairs). Per channel:
// 2 LDG.128 (x) + 2 LDG.64 (cb bf16) + 8 LDC.128 -> 64 FMA2.
// bf16 cb keeps the combined x+cb working set (112 MB) inside L2, so the
// depth-1 register pipeline's ~300-cycle cover hides every load.
__global__ void __launch_bounds__(256, 2)
proj_kernel(const float* __restrict__ x, float* __restrict__ out) {
    const int tid  = threadIdx.x;
    const int vq   = tid & 63;           // v-quad (4 floats = 2 pairs)
    const int og   = tid >> 6;           // output group 0..3 (8 outputs each)
    const int t0   = blockIdx.y * 2;
    const int b    = blockIdx.z;
    const size_t CH = (size_t)288 * 512;

    const size_t base = ((size_t)b * 32 * 288 + t0) * 512
                        + blockIdx.x * 256 + vq * 4;
    const float* px = x + base;
    const unsigned short* pch = g_cbh + base;

    // epilogue operands loaded up front (latency hidden under the c-loop)
    const float* pcv = g_cv + ((size_t)b * 288 + t0) * 512
                       + blockIdx.x * 256 + vq * 4;
    U64 m2[2][2], imp[2];
    #pragma unroll
    for (int p = 0; p < 2; p++) {
        ulonglong2 cvq = *(const ulonglong2*)(pcv + (size_t)p * 512);
        m2[p][0] = add2(pack2(1.f), cvq.x);
        m2[p][1] = add2(pack2(1.f), cvq.y);
        imp[p] = pack2(g_imp[b * 288 + t0 + p]);
    }

    // accumulators: [point][output][half]
    U64 acc[2][8][2];
    #pragma unroll
    for (int p = 0; p < 2; p++)
        #pragma unroll
        for (int o = 0; o < 8; o++) {
            U64 bo = c_wp.bd[og * 8 + o];
            acc[p][o][0] = bo;
            acc[p][o][1] = bo;
        }

    // depth-1 register pipeline over channels
    ulonglong2 xv[2], xn[2];
    uint2 cw_[2], cn_[2];
    #pragma unroll
    for (int p = 0; p < 2; p++) {
        xv[p]  = *(const ulonglong2*)(px + (size_t)p * 512);
        cw_[p] = *(const uint2*)(pch + (size_t)p * 512);
    }
    for (int c = 0; c < 32; c++) {
        if (c < 31) {
            const float* nx = px + (size_t)(c + 1) * CH;
            const unsigned short* nch = pch + (size_t)(c + 1) * CH;
            #pragma unroll
            for (int p = 0; p < 2; p++) {
                xn[p]  = *(const ulonglong2*)(nx + (size_t)p * 512);
                cn_[p] = *(const uint2*)(nch + (size_t)p * 512);
            }
        }
        // expand bf16 cb to f32x2 once per channel
        U64 cbv[2][2];
        #pragma unroll
        for (int p = 0; p < 2; p++) {
            cbv[p][0] = bfexp(cw_[p].x);
            cbv[p][1] = bfexp(cw_[p].y);
        }
        const ulonglong2* wrow = c_wp.wd + c * 32 + og * 8;
        #pragma unroll
        for (int o = 0; o < 8; o++) {
            ulonglong2 w = wrow[o];          // one LDC.128 -> 8 FMA2
            #pragma unroll
            for (int p = 0; p < 2; p++) {
                acc[p][o][0] = fma2(w.x, xv[p].x, acc[p][o][0]);
                acc[p][o][1] = fma2(w.x, xv[p].y, acc[p][o][1]);
                acc[p][o][0] = fma2(w.y, cbv[p][0], acc[p][o][0]);
                acc[p][o][1] = fma2(w.y, cbv[p][1], acc[p][o][1]);
            }
        }
        #pragma unroll
        for (int p = 0; p < 2; p++) { xv[p] = xn[p]; cw_[p] = cn_[p]; }
    }

    // epilogue: out = acc * (1+cv) + impact   (STG.128)
    float* po = out + base + (size_t)(og * 8) * CH;
    #pragma unroll
    for (int o = 0; o < 8; o++)
        #pragma unroll
        for (int p = 0; p < 2; p++) {
            ulonglong2 r;
            r.x = fma2(acc[p][o][0], m2[p][0], imp[p]);
            r.y = fma2(acc[p][o][1], m2[p][1], imp[p]);
            *(ulonglong2*)(po + (size_t)o * CH + (size_t)p * 512) = r;
        }
}

// ---------------- launch ----------------
extern "C" void kernel_launch(void* const* d_in, const int* in_sizes, int n_in,
                              void* d_out, int out_size) {
    const float* flow   = (const float*)d_in[0];
    const float* events = (const float*)d_in[1];
    const float* x      = (const float*)d_in[2];
    const float* ef     = (const float*)d_in[3];
    const float* w1     = (const float*)d_in[4];
    const float* b1     = (const float*)d_in[5];
    const float* w2     = (const float*)d_in[6];
    const float* b2     = (const float*)d_in[7];
    const float* fw     = (const float*)d_in[8];
    const float* fb     = (const float*)d_in[9];
    float* out = (float*)d_out;

    scan_kernel<<<2101, 256>>>(x, flow, events, ef, w1, b1, w2, b2, fw, fb);

    void* src = nullptr;
    cudaGetSymbolAddress(&src, g_wp);
    cudaMemcpyToSymbolAsync(c_wp, src, sizeof(WPack), 0, cudaMemcpyDeviceToDevice);

    dim3 gB(2, 144, 4);   // (V/256, T/2, B)
    proj_kernel<<<gB, 256>>>(x, out);
}

// round 15
// speedup vs baseline: 1.0923x; 1.0142x over previous
#include <cuda_runtime.h>
#include <math.h>

typedef unsigned long long U64;

// ---------------- device scratch (static, no runtime allocs) ----------------
__device__ float g_cv[4 * 288 * 512];              // (B,T,V) rolling CV
__device__ float g_imp[4 * 288];                   // (B,T) summed event impact
__device__ unsigned short g_cbh[4 * 32 * 288 * 512]; // (B,C,T,V) pooled combo, bf16
struct WPack {
    ulonglong2 wd[1024];   // [c][o] = {dup(w1+I), dup(w2)}
    U64 bd[32];            // dup bias
};
__device__ WPack g_wp;
__constant__ WPack c_wp;

// ---------------- packed f32x2 helpers (sm_103a) ----------------
static __device__ __forceinline__ U64 pack2(float x) {
    unsigned int u = __float_as_uint(x);
    U64 r;
    asm("mov.b64 %0, {%1, %2};" : "=l"(r) : "r"(u), "r"(u));
    return r;
}
static __device__ __forceinline__ U64 fma2(U64 a, U64 b, U64 c) {
    U64 d;
    asm("fma.rn.f32x2 %0, %1, %2, %3;" : "=l"(d) : "l"(a), "l"(b), "l"(c));
    return d;
}
static __device__ __forceinline__ U64 add2(U64 a, U64 b) {
    U64 d;
    asm("add.rn.f32x2 %0, %1, %2;" : "=l"(d) : "l"(a), "l"(b));
    return d;
}
static __device__ __forceinline__ U64 mul2(U64 a, U64 b) {
    U64 d;
    asm("mul.rn.f32x2 %0, %1, %2;" : "=l"(d) : "l"(a), "l"(b));
    return d;
}
// f32x2 (U64) -> bf16x2 (u32), round-to-nearest
static __device__ __forceinline__ unsigned int cvt_bf16x2(U64 v) {
    unsigned int lo, hi, u;
    asm("mov.b64 {%0,%1}, %2;" : "=r"(lo), "=r"(hi) : "l"(v));
    asm("cvt.rn.satfinite.bf16x2.f32 %0, %1, %2;"
        : "=r"(u) : "f"(__uint_as_float(hi)), "f"(__uint_as_float(lo)));
    return u;
}
// bf16x2 (u32) -> f32x2 (U64) by mantissa shift (exact)
static __device__ __forceinline__ U64 bfexp(unsigned int u) {
    unsigned int lo = u << 16;
    unsigned int hi = u & 0xFFFF0000u;
    U64 r;
    asm("mov.b64 %0, {%1, %2};" : "=l"(r) : "r"(lo), "r"(hi));
    return r;
}
static __device__ __forceinline__ void cp16(unsigned int s, const void* g) {
    asm volatile("cp.async.ca.shared.global [%0], [%1], 16;" :: "r"(s), "l"(g));
}
static __device__ __forceinline__ void cp8(unsigned int s, const void* g) {
    asm volatile("cp.async.ca.shared.global [%0], [%1], 8;" :: "r"(s), "l"(g));
}

// ================= kernel A: prep blocks FIRST, then scan/pool blocks =================
// blocks [0, 48):    rolling CV       (wave 1 -> overlapped by the scan body)
// blocks [48, 52):   event impact     (events staged through SMEM)
// block  52:         weight packing
// blocks [53, 2101): per-(b,c,vtile) full-T prefix scan + pooled combination
__global__ void __launch_bounds__(256)
scan_kernel(const float* __restrict__ x,
            const float* __restrict__ flow,
            const float* __restrict__ events,
            const float* __restrict__ ef,
            const float* __restrict__ w1,
            const float* __restrict__ b1,
            const float* __restrict__ w2,
            const float* __restrict__ b2,
            const float* __restrict__ fusion_w,
            const float* __restrict__ fusion_b) {
    __shared__ U64 s_ps[289][16];   // 37KB (also reused by the impact branch)
    __shared__ float s_h[32];
    __shared__ float s_lg[5];

    const int bid = blockIdx.x;
    const int tid = threadIdx.x;

    if (bid < 53) {
        if (bid < 48) {
            // ---- rolling CV: (b, 24-t chunk), thread covers v=tid and v=tid+256
            const int b = bid / 12;
            const int c0 = (bid % 12) * 24;
            const float* f0 = flow + (size_t)b * 288 * 512 + tid;
            const float* f1 = f0 + 256;
            int tstart = c0 - 59; if (tstart < 0) tstart = 0;
            float sA = 0.f, s2A = 0.f, sB = 0.f, s2B = 0.f;
            for (int t = tstart; t < c0 + 24; t++) {
                float a0 = f0[(size_t)t * 512];
                float a1 = f1[(size_t)t * 512];
                int to = t - 60;
                float o0 = 0.f, o1 = 0.f;
                bool sub = (to >= tstart);
                if (sub) { o0 = f0[(size_t)to * 512]; o1 = f1[(size_t)to * 512]; }
                sA += a0; s2A += a0 * a0; sB += a1; s2B += a1 * a1;
                if (sub) { sA -= o0; s2A -= o0 * o0; sB -= o1; s2B -= o1 * o1; }
                if (t >= c0) {
                    float cv0 = 0.f, cv1 = 0.f;
                    if (t >= 59) {
                        float m0 = sA * (1.f / 60.f);
                        float v0 = (s2A - 60.f * m0 * m0) * (1.f / 59.f);
                        cv0 = sqrtf(fmaxf(v0, 0.f)) / (m0 + 1e-6f);
                        float m1 = sB * (1.f / 60.f);
                        float v1 = (s2B - 60.f * m1 * m1) * (1.f / 59.f);
                        cv1 = sqrtf(fmaxf(v1, 0.f)) / (m1 + 1e-6f);
                    }
                    size_t o = ((size_t)b * 288 + t) * 512 + tid;
                    g_cv[o] = cv0;
                    g_cv[o + 256] = cv1;
                }
            }
        } else if (bid < 52) {
            // ---- event impact: stage events[b] into SMEM, suffix-sum from SMEM
            const int b = bid - 48;
            float* s_ev = (float*)s_ps;   // 864 floats
            for (int i = tid; i < 864; i += 256)
                s_ev[i] = events[(size_t)b * 864 + i];
            __syncthreads();
            const float r0 = expf(-1.f / 300.f), r1 = expf(-1.f / 600.f),
                        r2 = expf(-1.f / 180.f);
            #pragma unroll
            for (int half = 0; half < 2; half++) {
                int t = tid + half * 256;
                if (t < 288) {
                    float w0 = 0.3f, w1v = 0.5f, w2v = 0.2f;
                    float a0 = 0.f, a1 = 0.f, a2 = 0.f;
                    for (int s = t; s < 288; s++) {
                        const float* e = s_ev + s * 3;
                        a0 = fmaf(e[0], w0, a0);
                        a1 = fmaf(e[1], w1v, a1);
                        a2 = fmaf(e[2], w2v, a2);
                        w0 *= r0; w1v *= r1; w2v *= r2;
                    }
                    g_imp[b * 288 + t] = a0 + a1 + a2;
                }
            }
        } else {
            // ---- weight packing (residual identity folded into w1)
            for (int i = tid; i < 1024; i += 256) {
                int c = i >> 5, o = i & 31;
                float a = fusion_w[o * 64 + c] + ((o == c) ? 1.f : 0.f);
                float bw = fusion_w[o * 64 + 32 + c];
                ulonglong2 p;
                p.x = pack2(a);
                p.y = pack2(bw);
                g_wp.wd[i] = p;
            }
            if (tid < 32) g_wp.bd[tid] = pack2(fusion_b[tid]);
        }
        return;
    }

    // ---------------- scan/pool block ----------------
    const int sid = bid - 53;
    const int v0 = (sid & 15) * 32;        // 16 v-pairs
    const int c  = (sid >> 4) & 31;
    const int b  = sid >> 9;

    // load full T column for this (b,c,v-tile)
    const float* xb = x + ((size_t)(b * 32 + c) * 288) * 512 + v0;
    #pragma unroll
    for (int k = 0; k < 18; k++) {
        int idx = tid + k * 256;
        int r = idx >> 4, cl = idx & 15;
        s_ps[1 + r][cl] = *(const U64*)(xb + (size_t)r * 512 + cl * 2);
    }
    if (tid < 16) s_ps[0][tid] = 0ull;

    // gate MLP hidden layer (inline; no prep dependency)
    if (tid < 32) {
        float a = b1[tid];
        #pragma unroll
        for (int i = 0; i < 8; i++) a += ef[b * 8 + i] * w1[i * 32 + tid];
        s_h[tid] = fmaxf(a, 0.f);
    }
    __syncthreads();

    if (tid < 5) {
        float a = b2[tid];
        #pragma unroll
        for (int i = 0; i < 32; i++) a += s_h[i] * w2[i * 5 + tid];
        s_lg[tid] = 1.f / (1.f + expf(-a));
    }

    // phase 1: in-segment inclusive scan (16 segments x 18 rows)
    const int seg = tid >> 4, cl = tid & 15;
    {
        int r0 = 1 + seg * 18;
        U64 run = 0ull;
        #pragma unroll
        for (int i = 0; i < 18; i++) {
            run = add2(run, s_ps[r0 + i][cl]);
            s_ps[r0 + i][cl] = run;
        }
    }
    __syncthreads();

    // phase 2a: per-thread segment-offset gather
    U64 off = 0ull;
    if (seg > 0) {
        off = s_ps[18][cl];
        for (int s = 2; s <= seg; s++) off = add2(off, s_ps[18 * s][cl]);
    }
    __syncthreads();

    // phase 2b: apply offsets; finalize gate weights in registers
    if (seg > 0) {
        int r0 = 1 + seg * 18;
        #pragma unroll
        for (int i = 0; i < 18; i++)
            s_ps[r0 + i][cl] = add2(s_ps[r0 + i][cl], off);
    }
    float lg0 = s_lg[0], lg1 = s_lg[1], lg2 = s_lg[2], lg3 = s_lg[3], lg4 = s_lg[4];
    float mx = fmaxf(fmaxf(fmaxf(lg0, lg1), fmaxf(lg2, lg3)), lg4);
    float e0 = expf(lg0 - mx), e1 = expf(lg1 - mx), e2 = expf(lg2 - mx),
          e3 = expf(lg3 - mx), e4 = expf(lg4 - mx);
    float inv = 1.f / (e0 + e1 + e2 + e3 + e4);
    U64 cw[5];
    cw[0] = pack2(e0 * inv * (1.f / 3.f));
    cw[1] = pack2(e1 * inv * (1.f / 6.f));
    cw[2] = pack2(e2 * inv * (1.f / 12.f));
    cw[3] = pack2(e3 * inv * (1.f / 24.f));
    cw[4] = pack2(e4 * inv * (1.f / 48.f));
    __syncthreads();

    // compute cb for all (t, v-pair) and store as bf16x2
    const U64 neg1 = pack2(-1.f);
    unsigned short* cbase = g_cbh + ((size_t)(b * 32 + c) * 288) * 512 + v0;
    #pragma unroll
    for (int k = 0; k < 18; k++) {
        int idx = tid + k * 256;
        int t = idx >> 4, cl2 = idx & 15;
        int a3  = max(t - 1, 0),  b3  = min(t + 2, 288);
        int a6  = max(t - 3, 0),  b6  = min(t + 3, 288);
        int a12 = max(t - 6, 0),  b12 = min(t + 6, 288);
        int a24 = max(t - 12, 0), b24 = min(t + 12, 288);
        int a48 = max(t - 24, 0), b48 = min(t + 24, 288);
        U64 d0 = fma2(neg1, s_ps[a3][cl2],  s_ps[b3][cl2]);
        U64 d1 = fma2(neg1, s_ps[a6][cl2],  s_ps[b6][cl2]);
        U64 d2 = fma2(neg1, s_ps[a12][cl2], s_ps[b12][cl2]);
        U64 d3 = fma2(neg1, s_ps[a24][cl2], s_ps[b24][cl2]);
        U64 d4 = fma2(neg1, s_ps[a48][cl2], s_ps[b48][cl2]);
        U64 cb = mul2(cw[0], d0);
        cb = fma2(cw[1], d1, cb);
        cb = fma2(cw[2], d2, cb);
        cb = fma2(cw[3], d3, cb);
        cb = fma2(cw[4], d4, cb);
        *(unsigned int*)(cbase + (size_t)t * 512 + cl2 * 2) = cvt_bf16x2(cb);
    }
}

// ---------------- kernel B: pointwise 64->32 projection, cp.async ring ----------------
// Thread = (8 outputs) x (2 t-points) x (2 v-pairs). 64 loader threads fill a
// 4-stage SMEM ring via cp.async, issued 3 channels ahead -> load latency fully
// hidden without register-pipeline pressure. All threads consume via LDS.
__global__ void __launch_bounds__(256, 2)
proj_kernel(const float* __restrict__ x, float* __restrict__ out) {
    __shared__ ulonglong2 s_x[4][2][64];   // [stage][t-point][vq] 16B  (8 KB)
    __shared__ uint2      s_c[4][2][64];   // [stage][t-point][vq]  8B  (4 KB)

    const int tid  = threadIdx.x;
    const int vq   = tid & 63;           // v-quad (4 floats = 2 pairs)
    const int og   = tid >> 6;           // output group 0..3 (8 outputs each)
    const int t0   = blockIdx.y * 2;
    const int b    = blockIdx.z;
    const size_t CH = (size_t)288 * 512;
    const bool loader = (og == 0);

    const size_t base = ((size_t)b * 32 * 288 + t0) * 512
                        + blockIdx.x * 256 + vq * 4;
    const float* px = x + base;
    const unsigned short* pch = g_cbh + base;

    // prologue: stages 0..2 in flight
    if (loader) {
        #pragma unroll
        for (int s = 0; s < 3; s++) {
            #pragma unroll
            for (int p = 0; p < 2; p++) {
                cp16((unsigned int)__cvta_generic_to_shared(&s_x[s][p][vq]),
                     px + (size_t)s * CH + (size_t)p * 512);
                cp8((unsigned int)__cvta_generic_to_shared(&s_c[s][p][vq]),
                    pch + (size_t)s * CH + (size_t)p * 512);
            }
            asm volatile("cp.async.commit_group;");
        }
    }

    // epilogue operands loaded up front (latency hidden under the c-loop)
    const float* pcv = g_cv + ((size_t)b * 288 + t0) * 512
                       + blockIdx.x * 256 + vq * 4;
    U64 m2[2][2], imp[2];
    #pragma unroll
    for (int p = 0; p < 2; p++) {
        ulonglong2 cvq = *(const ulonglong2*)(pcv + (size_t)p * 512);
        m2[p][0] = add2(pack2(1.f), cvq.x);
        m2[p][1] = add2(pack2(1.f), cvq.y);
        imp[p] = pack2(g_imp[b * 288 + t0 + p]);
    }

    // accumulators: [point][output][half]
    U64 acc[2][8][2];
    #pragma unroll
    for (int p = 0; p < 2; p++)
        #pragma unroll
        for (int o = 0; o < 8; o++) {
            U64 bo = c_wp.bd[og * 8 + o];
            acc[p][o][0] = bo;
            acc[p][o][1] = bo;
        }

    for (int c = 0; c < 32; c++) {
        if (loader) asm volatile("cp.async.wait_group 2;");
        __syncthreads();
        const int sl = c & 3;

        // consume stage sl from smem
        ulonglong2 xv[2];
        U64 cbv[2][2];
        #pragma unroll
        for (int p = 0; p < 2; p++) {
            xv[p] = s_x[sl][p][vq];
            uint2 cq = s_c[sl][p][vq];
            cbv[p][0] = bfexp(cq.x);
            cbv[p][1] = bfexp(cq.y);
        }

        // refill slot (c+3)&3 — consumed at iteration c-1, one barrier ago
        if (loader && c + 3 < 32) {
            const int sn = (c + 3) & 3;
            #pragma unroll
            for (int p = 0; p < 2; p++) {
                cp16((unsigned int)__cvta_generic_to_shared(&s_x[sn][p][vq]),
                     px + (size_t)(c + 3) * CH + (size_t)p * 512);
                cp8((unsigned int)__cvta_generic_to_shared(&s_c[sn][p][vq]),
                    pch + (size_t)(c + 3) * CH + (size_t)p * 512);
            }
            asm volatile("cp.async.commit_group;");
        }

        const ulonglong2* wrow = c_wp.wd + c * 32 + og * 8;
        #pragma unroll
        for (int o = 0; o < 8; o++) {
            ulonglong2 w = wrow[o];          // one LDC.128 -> 8 FMA2
            #pragma unroll
            for (int p = 0; p < 2; p++) {
                acc[p][o][0] = fma2(w.x, xv[p].x, acc[p][o][0]);
                acc[p][o][1] = fma2(w.x, xv[p].y, acc[p][o][1]);
                acc[p][o][0] = fma2(w.y, cbv[p][0], acc[p][o][0]);
                acc[p][o][1] = fma2(w.y, cbv[p][1], acc[p][o][1]);
            }
        }
    }

    // epilogue: out = acc * (1+cv) + impact   (STG.128)
    float* po = out + base + (size_t)(og * 8) * CH;
    #pragma unroll
    for (int o = 0; o < 8; o++)
        #pragma unroll
        for (int p = 0; p < 2; p++) {
            ulonglong2 r;
            r.x = fma2(acc[p][o][0], m2[p][0], imp[p]);
            r.y = fma2(acc[p][o][1], m2[p][1], imp[p]);
            *(ulonglong2*)(po + (size_t)o * CH + (size_t)p * 512) = r;
        }
}

// ---------------- launch ----------------
extern "C" void kernel_launch(void* const* d_in, const int* in_sizes, int n_in,
                              void* d_out, int out_size) {
    const float* flow   = (const float*)d_in[0];
    const float* events = (const float*)d_in[1];
    const float* x      = (const float*)d_in[2];
    const float* ef     = (const float*)d_in[3];
    const float* w1     = (const float*)d_in[4];
    const float* b1     = (const float*)d_in[5];
    const float* w2     = (const float*)d_in[6];
    const float* b2     = (const float*)d_in[7];
    const float* fw     = (const float*)d_in[8];
    const float* fb     = (const float*)d_in[9];
    float* out = (float*)d_out;

    scan_kernel<<<2101, 256>>>(x, flow, events, ef, w1, b1, w2, b2, fw, fb);

    void* src = nullptr;
    cudaGetSymbolAddress(&src, g_wp);
    cudaMemcpyToSymbolAsync(c_wp, src, sizeof(WPack), 0, cudaMemcpyDeviceToDevice);

    dim3 gB(2, 144, 4);   // (V/256, T/2, B)
    proj_kernel<<<gB, 256>>>(x, out);
}